// round 2
// baseline (speedup 1.0000x reference)
#include <cuda_runtime.h>
#include <cstdint>

// Problem dims
#define Sn 1024
#define Bn 64
#define Dn 256
#define Hn 256
#define G4 1024               // 4*H gate columns
#define BH (Bn*Hn)            // 16384
#define NBLK 128              // blocks in persistent recurrence kernel

// ---------------- scratch (static device allocations only) ----------------
__device__ float g_P[(size_t)Sn * G4 * Bn];     // [t][c][b], c = g*256+j  (256 MB)
__device__ float g_ysT[(size_t)Sn * Hn * Bn];   // h_t history TRANSPOSED [t][j][b] (64 MB)
__device__ float g_Wxr[G4 * Dn];                // [c][k]  x-part weights reordered
__device__ float g_WhT[NBLK * Hn * 8];          // [bk][k][ci]  h-part weights, ci=jj*4+g
__device__ float g_thb[G4];                     // b + theta folded
__device__ float g_cT[Hn * Bn];                 // final cell state [j][b]
__device__ int   g_bar;                         // grid barrier counter (monotonic per launch)

// ---------------- prep: reorder weights, fold bias+theta, reset barrier ----------------
__global__ void prep_kernel(const float* Wf, const float* bf,
                            const float* Wi, const float* bi,
                            const float* Wu, const float* bu,
                            const float* Wo, const float* bo,
                            const float* thf, const float* thi,
                            const float* thu, const float* tho) {
    int idx = blockIdx.x * blockDim.x + threadIdx.x;
    const float* W[4]  = {Wf, Wi, Wu, Wo};
    const float* bb[4] = {bf, bi, bu, bo};
    const float* th[4] = {thf, thi, thu, tho};
    if (idx < G4 * Dn) {                        // Wxr[c][k] = W_g[j][k], c=g*256+j
        int c = idx >> 8, k = idx & 255;
        int g = c >> 8, j = c & 255;
        g_Wxr[idx] = W[g][j * 512 + k];
    }
    if (idx < NBLK * Hn * 8) {                  // WhT[bk][k][ci] = W_g[j][256+k]
        int bk = idx >> 11, rem = idx & 2047;
        int k = rem >> 3, ci = rem & 7;
        int jj = ci >> 2, g = ci & 3;
        int j = bk * 2 + jj;
        g_WhT[idx] = W[g][j * 512 + 256 + k];
    }
    if (idx < G4) {
        int g = idx >> 8, j = idx & 255;
        g_thb[idx] = bb[g][j] + th[g][j];
    }
    if (idx == 0) g_bar = 0;
}

// ---------------- phase 1: X projection SGEMM (65536 x 1024 x 256) ----------------
// C[m][n] = X[m][:] . Wxr[n][:] + thb[n], written transposed into g_P[t][c][b]
__global__ void __launch_bounds__(256) xproj_kernel(const float* __restrict__ X) {
    __shared__ float As[16][128];
    __shared__ float Bs[16][128];
    int tid = threadIdx.x;
    int n0 = blockIdx.x * 128;
    int m0 = blockIdx.y * 128;
    int tx = tid & 15, ty = tid >> 4;
    float acc[8][8];
#pragma unroll
    for (int i = 0; i < 8; i++)
#pragma unroll
        for (int j = 0; j < 8; j++) acc[i][j] = 0.0f;

    for (int k0 = 0; k0 < 256; k0 += 16) {
#pragma unroll
        for (int i = 0; i < 2; i++) {
            int fidx = tid + i * 256;           // 0..511
            int r = fidx >> 2, kq = (fidx & 3) * 4;
            float4 va = *(const float4*)&X[(size_t)(m0 + r) * 256 + k0 + kq];
            As[kq + 0][r] = va.x; As[kq + 1][r] = va.y;
            As[kq + 2][r] = va.z; As[kq + 3][r] = va.w;
            float4 vb = *(const float4*)&g_Wxr[(size_t)(n0 + r) * 256 + k0 + kq];
            Bs[kq + 0][r] = vb.x; Bs[kq + 1][r] = vb.y;
            Bs[kq + 2][r] = vb.z; Bs[kq + 3][r] = vb.w;
        }
        __syncthreads();
#pragma unroll
        for (int kk = 0; kk < 16; kk++) {
            float a[8], b[8];
#pragma unroll
            for (int i = 0; i < 8; i++) a[i] = As[kk][ty * 8 + i];
#pragma unroll
            for (int j = 0; j < 8; j++) b[j] = Bs[kk][tx * 8 + j];
#pragma unroll
            for (int i = 0; i < 8; i++)
#pragma unroll
                for (int j = 0; j < 8; j++) acc[i][j] += a[i] * b[j];
        }
        __syncthreads();
    }
#pragma unroll
    for (int i = 0; i < 8; i++) {
        int m = m0 + ty * 8 + i;
        int t = m >> 6, bb2 = m & 63;
        size_t base = (size_t)t * (G4 * Bn) + bb2;
#pragma unroll
        for (int j = 0; j < 8; j++) {
            int c = n0 + tx * 8 + j;
            g_P[base + (size_t)c * Bn] = acc[i][j] + g_thb[c];
        }
    }
}

// ---------------- phase 2: persistent LSTM recurrence ----------------
// One launch. 128 blocks x 256 threads, all co-resident (<=148 SMs).
// Block bk owns hidden units j0=2*bk, j0+1 (8 gate rows). Weights in smem once.
// Per step: software grid barrier, stage h[t-1] (64KB smem), 8 warps compute
// partial dot products with packed fp32x2 FMA, 128 threads finalize gates +
// cell update (cell kept in registers across all 1024 steps).
#define SMEM_MAIN_FLOATS (Hn * Bn + Hn * 8 + 8 * 256)
#define SMEM_MAIN_BYTES  (SMEM_MAIN_FLOATS * 4)

__global__ void __launch_bounds__(256) lstm_main_kernel() {
    extern __shared__ float sm[];
    float* shH   = sm;                    // [256 k][64 b]
    float* shW   = sm + Hn * Bn;          // [256 k][8 c]
    float* shRed = shW + Hn * 8;          // [8 warp][8 c][32 lane]
    int tid = threadIdx.x;
    int bk = blockIdx.x;

    // load weights once (2048 floats)
    {
        const float4* wsrc = (const float4*)(g_WhT + (size_t)bk * 2048);
        float4* wdst = (float4*)shW;
        wdst[tid]       = wsrc[tid];
        wdst[tid + 256] = wsrc[tid + 256];
    }

    int warp = tid >> 5, lane = tid & 31;
    int bg = warp & 1, kc = warp >> 1;       // b-half, k-chunk
    int fb = tid & 63;                        // finalize: batch
    int fj = tid >> 6;                        // finalize: jj (valid for tid<128)
    float cell = 0.0f;

    __syncthreads();

    for (int t = 0; t < Sn; t++) {
        // prefetch P[t] for finalize threads (independent of barrier)
        float p0, p1, p2, p3;
        if (tid < 128) {
            size_t pb = (size_t)t * 65536 + (size_t)(bk * 2 + fj) * 64 + fb;
            p0 = g_P[pb];
            p1 = g_P[pb + 16384];
            p2 = g_P[pb + 32768];
            p3 = g_P[pb + 49152];
        }
        if (t > 0) {
            if (tid == 0) {
                int target = NBLK * t;
                while (*(volatile int*)&g_bar < target) { }
            }
            __syncthreads();
            __threadfence();
            // stage h[t-1] transposed [k][b] into smem (coalesced)
            {
                const float4* hs = (const float4*)(g_ysT + (size_t)(t - 1) * BH);
                float4* hd = (float4*)shH;
#pragma unroll
                for (int i = 0; i < 16; i++) hd[tid + i * 256] = hs[tid + i * 256];
            }
            __syncthreads();
            // compute: warp (bg,kc) -> partial pre[c=0..7][b=bg*32+lane] over 64 k
            const float* hrow = shH + kc * 64 * Bn + bg * 32 + lane;
            const float* wrow = shW + kc * 64 * 8;
            unsigned long long a01 = 0, a23 = 0, a45 = 0, a67 = 0;
#pragma unroll 8
            for (int k = 0; k < 64; k++) {
                float hv = hrow[k * Bn];
                unsigned long long h2;
                asm("mov.b64 %0, {%1, %1};" : "=l"(h2) : "r"(__float_as_uint(hv)));
                const ulonglong2* wp = (const ulonglong2*)(wrow + k * 8);
                ulonglong2 wA = wp[0];
                ulonglong2 wB = wp[1];
                asm("fma.rn.f32x2 %0, %1, %2, %0;" : "+l"(a01) : "l"(wA.x), "l"(h2));
                asm("fma.rn.f32x2 %0, %1, %2, %0;" : "+l"(a23) : "l"(wA.y), "l"(h2));
                asm("fma.rn.f32x2 %0, %1, %2, %0;" : "+l"(a45) : "l"(wB.x), "l"(h2));
                asm("fma.rn.f32x2 %0, %1, %2, %0;" : "+l"(a67) : "l"(wB.y), "l"(h2));
            }
            // unpack + store partials: shRed[warp*256 + c*32 + lane]
            {
                float* rp = shRed + warp * 256 + lane;
                unsigned int lo, hi;
                asm("mov.b64 {%0, %1}, %2;" : "=r"(lo), "=r"(hi) : "l"(a01));
                rp[0]   = __uint_as_float(lo); rp[32]  = __uint_as_float(hi);
                asm("mov.b64 {%0, %1}, %2;" : "=r"(lo), "=r"(hi) : "l"(a23));
                rp[64]  = __uint_as_float(lo); rp[96]  = __uint_as_float(hi);
                asm("mov.b64 {%0, %1}, %2;" : "=r"(lo), "=r"(hi) : "l"(a45));
                rp[128] = __uint_as_float(lo); rp[160] = __uint_as_float(hi);
                asm("mov.b64 {%0, %1}, %2;" : "=r"(lo), "=r"(hi) : "l"(a67));
                rp[192] = __uint_as_float(lo); rp[224] = __uint_as_float(hi);
            }
            __syncthreads();
        }
        // finalize: thread (fj, fb) owns hidden unit j = 2*bk + fj, batch fb
        if (tid < 128) {
            float s0 = p0, s1 = p1, s2 = p2, s3 = p3;
            if (t > 0) {
                int bg2 = fb >> 5, ln2 = fb & 31;
                int cbase = fj * 4;
#pragma unroll
                for (int kc2 = 0; kc2 < 4; kc2++) {
                    const float* rp = shRed + (kc2 * 2 + bg2) * 256 + ln2;
                    s0 += rp[(cbase + 0) * 32];
                    s1 += rp[(cbase + 1) * 32];
                    s2 += rp[(cbase + 2) * 32];
                    s3 += rp[(cbase + 3) * 32];
                }
            }
            float f  = 1.0f / (1.0f + __expf(-__cosf(s0)));
            float ii = 1.0f / (1.0f + __expf(-__cosf(s1)));
            float u  = tanhf(__cosf(s2));
            float o  = 1.0f / (1.0f + __expf(-__cosf(s3)));
            cell = f * cell + ii * u;
            g_ysT[(size_t)t * BH + (size_t)(bk * 2 + fj) * 64 + fb] = o * tanhf(cell);
        }
        __syncthreads();
        if (tid == 0) {
            __threadfence();
            atomicAdd(&g_bar, 1);
        }
    }
    if (tid < 128) g_cT[(size_t)(bk * 2 + fj) * 64 + fb] = cell;
}

// ---------------- phase 3a: qfeat = cos(ysT + phi), transpose to [B][S][H] ----------------
__global__ void __launch_bounds__(256) qfeat_kernel(const float* __restrict__ phi,
                                                    float* __restrict__ out) {
    __shared__ float smq[64 * 129];
    int s = blockIdx.x, half = blockIdx.y;
    int h0 = half * 128;
    int tid = threadIdx.x;
    const float* src = g_ysT + (size_t)s * BH + (size_t)h0 * 64;
#pragma unroll
    for (int r = 0; r < 32; r++) {
        int i = tid + r * 256;                // 0..8191, coalesced over b
        int h = i >> 6, b = i & 63;
        smq[b * 129 + h] = __cosf(src[i] + phi[h0 + h]);
    }
    __syncthreads();
#pragma unroll
    for (int r = 0; r < 32; r++) {
        int i = tid + r * 256;                // coalesced over h
        int b = i >> 7, h = i & 127;
        out[(size_t)b * (Sn * Hn) + (size_t)s * Hn + h0 + h] = smq[b * 129 + h];
    }
}

// ---------------- phase 3b: attention context + residual add ----------------
// softmax(tanh(cos(q+th))) over s: tanh in [-1,1] so exp without max-sub is exact.
__global__ void attn_kernel(const float* __restrict__ tha, float* __restrict__ out) {
    int b = blockIdx.x, h = threadIdx.x;
    float th = tha[h];
    float se = 0.0f, sq = 0.0f;
    size_t base = (size_t)b * Sn * Hn + h;
#pragma unroll 4
    for (int s = 0; s < Sn; s++) {
        float q = out[base + (size_t)s * Hn];
        float e = __expf(tanhf(__cosf(q + th)));
        se += e; sq += e * q;
    }
    float ctx = sq / se;
#pragma unroll 4
    for (int s = 0; s < Sn; s++) {
        out[base + (size_t)s * Hn] += ctx;
    }
}

// ---------------- phase 3c: hx, cx tail (transpose back to [b][j]) ----------------
__global__ void tail_kernel(float* __restrict__ out) {
    int i = blockIdx.x * blockDim.x + threadIdx.x;
    if (i < BH) {
        int b = i >> 8, jx = i & 255;
        out[(size_t)Bn * Sn * Hn + i]      = g_ysT[(size_t)(Sn - 1) * BH + jx * 64 + b];
        out[(size_t)Bn * Sn * Hn + BH + i] = g_cT[jx * 64 + b];
    }
}

// ---------------- launch ----------------
extern "C" void kernel_launch(void* const* d_in, const int* in_sizes, int n_in,
                              void* d_out, int out_size) {
    const float* X   = (const float*)d_in[0];
    const float* Wf  = (const float*)d_in[1];
    const float* bf  = (const float*)d_in[2];
    const float* Wi  = (const float*)d_in[3];
    const float* bi  = (const float*)d_in[4];
    const float* Wu  = (const float*)d_in[5];
    const float* bu  = (const float*)d_in[6];
    const float* Wo  = (const float*)d_in[7];
    const float* bo  = (const float*)d_in[8];
    const float* thf = (const float*)d_in[9];
    const float* thi = (const float*)d_in[10];
    const float* thu = (const float*)d_in[11];
    const float* tho = (const float*)d_in[12];
    const float* phi = (const float*)d_in[13];
    const float* tha = (const float*)d_in[14];
    float* out = (float*)d_out;

    cudaFuncSetAttribute(lstm_main_kernel,
                         cudaFuncAttributeMaxDynamicSharedMemorySize, SMEM_MAIN_BYTES);

    prep_kernel<<<1024, 256>>>(Wf, bf, Wi, bi, Wu, bu, Wo, bo, thf, thi, thu, tho);
    xproj_kernel<<<dim3(8, 512), 256>>>(X);
    lstm_main_kernel<<<NBLK, 256, SMEM_MAIN_BYTES>>>();
    qfeat_kernel<<<dim3(Sn, 2), 256>>>(phi, out);
    attn_kernel<<<Bn, 256>>>(tha, out);
    if (out_size >= Bn * Sn * Hn + 2 * BH) {
        tail_kernel<<<64, 256>>>(out);
    }
}

// round 3
// speedup vs baseline: 1.1067x; 1.1067x over previous
#include <cuda_runtime.h>
#include <cstdint>

// Problem dims
#define Sn 1024
#define Bn 64
#define Dn 256
#define Hn 256
#define G4 1024               // 4*H gate columns
#define BH (Bn*Hn)            // 16384
#define GB 16                 // batch groups (4 batches each)
#define GJ 8                  // j groups (32 hidden units each) == cluster size
#define NBLK (GB*GJ)          // 128 blocks

// ---------------- scratch (static device allocations only) ----------------
__device__ float g_P[(size_t)Sn * G4 * Bn];     // [t][ig][jg][g][jl][bl] (256 MB)
__device__ float g_ysT[(size_t)Sn * Hn * Bn];   // h history [t][j][b] (64 MB)
__device__ float g_Wxr[G4 * Dn];                // [c][k] x-part weights (c=g*256+j)
__device__ float g_Wh2[GJ * Hn * 128];          // [jg][k][cl] h-part weights, cl=jl*4+g
__device__ float g_thb[G4];                     // b + theta folded
__device__ float g_cT[Hn * Bn];                 // final cell state [j][b]

// ---------------- prep ----------------
__global__ void prep_kernel(const float* Wf, const float* bf,
                            const float* Wi, const float* bi,
                            const float* Wu, const float* bu,
                            const float* Wo, const float* bo,
                            const float* thf, const float* thi,
                            const float* thu, const float* tho) {
    int idx = blockIdx.x * blockDim.x + threadIdx.x;
    const float* W[4]  = {Wf, Wi, Wu, Wo};
    const float* bb[4] = {bf, bi, bu, bo};
    const float* th[4] = {thf, thi, thu, tho};
    if (idx < G4 * Dn) {                        // Wxr[c][k] = W_g[j][k], c=g*256+j
        int c = idx >> 8, k = idx & 255;
        int g = c >> 8, j = c & 255;
        g_Wxr[idx] = W[g][j * 512 + k];
    }
    if (idx < GJ * Hn * 128) {                  // Wh2[jg][k][cl] = W_g[jg*32+jl][256+k]
        int jg = idx >> 15, rem = idx & 32767;
        int k = rem >> 7, cl = rem & 127;
        int jl = cl >> 2, g = cl & 3;
        int j = jg * 32 + jl;
        g_Wh2[idx] = W[g][j * 512 + 256 + k];
    }
    if (idx < G4) {
        int g = idx >> 8, j = idx & 255;
        g_thb[idx] = bb[g][j] + th[g][j];
    }
}

// ---------------- phase 1: X projection SGEMM (65536 x 1024 x 256) ----------------
__global__ void __launch_bounds__(256) xproj_kernel(const float* __restrict__ X) {
    __shared__ float As[16][128];
    __shared__ float Bs[16][128];
    int tid = threadIdx.x;
    int n0 = blockIdx.x * 128;
    int m0 = blockIdx.y * 128;
    int tx = tid & 15, ty = tid >> 4;
    float acc[8][8];
#pragma unroll
    for (int i = 0; i < 8; i++)
#pragma unroll
        for (int j = 0; j < 8; j++) acc[i][j] = 0.0f;

    for (int k0 = 0; k0 < 256; k0 += 16) {
#pragma unroll
        for (int i = 0; i < 2; i++) {
            int fidx = tid + i * 256;
            int r = fidx >> 2, kq = (fidx & 3) * 4;
            float4 va = *(const float4*)&X[(size_t)(m0 + r) * 256 + k0 + kq];
            As[kq + 0][r] = va.x; As[kq + 1][r] = va.y;
            As[kq + 2][r] = va.z; As[kq + 3][r] = va.w;
            float4 vb = *(const float4*)&g_Wxr[(size_t)(n0 + r) * 256 + k0 + kq];
            Bs[kq + 0][r] = vb.x; Bs[kq + 1][r] = vb.y;
            Bs[kq + 2][r] = vb.z; Bs[kq + 3][r] = vb.w;
        }
        __syncthreads();
#pragma unroll
        for (int kk = 0; kk < 16; kk++) {
            float a[8], b[8];
#pragma unroll
            for (int i = 0; i < 8; i++) a[i] = As[kk][ty * 8 + i];
#pragma unroll
            for (int j = 0; j < 8; j++) b[j] = Bs[kk][tx * 8 + j];
#pragma unroll
            for (int i = 0; i < 8; i++)
#pragma unroll
                for (int j = 0; j < 8; j++) acc[i][j] += a[i] * b[j];
        }
        __syncthreads();
    }
#pragma unroll
    for (int i = 0; i < 8; i++) {
        int m = m0 + ty * 8 + i;
        int t = m >> 6, b = m & 63;
        int ig = b >> 2, bl = b & 3;
#pragma unroll
        for (int j = 0; j < 8; j++) {
            int c = n0 + tx * 8 + j;
            int g = c >> 8, jj = c & 255;
            int jg = jj >> 5, jl = jj & 31;
            size_t idx = ((((size_t)t * GB + ig) * GJ + jg) << 9) + g * 128 + jl * 4 + bl;
            g_P[idx] = acc[i][j] + g_thb[c];
        }
    }
}

// ---------------- phase 2: clustered persistent LSTM recurrence ----------------
// 128 blocks = 16 clusters of 8. Cluster = one batch group (4 batches).
// Block rank jg owns 32 hidden units (128 gate cols). Weights resident in smem.
// h exchange via DSMEM + cluster-scope mbarrier (double-buffered).
// smem float layout: [0..3] mbar/pad | shH[2][256][4] | shRed[4][64][10] | shW[256][128]
#define SHH_OFF   4
#define SHRED_OFF (SHH_OFF + 2048)
#define SHW_OFF   (SHRED_OFF + 2560)
#define SMEM_MAIN_FLOATS (SHW_OFF + 32768)
#define SMEM_MAIN_BYTES  (SMEM_MAIN_FLOATS * 4)

__global__ void __launch_bounds__(256, 1) __cluster_dims__(GJ, 1, 1)
lstm_main_kernel() {
    extern __shared__ float sm[];
    int tid = threadIdx.x;
    uint32_t jg;
    asm("mov.u32 %0, %%cluster_ctarank;" : "=r"(jg));
    int ig = blockIdx.x >> 3;

    uint32_t sbase;
    asm("{ .reg .u64 t0; cvta.to.shared.u64 t0, %1; cvt.u32.u64 %0, t0; }"
        : "=r"(sbase) : "l"(sm));
    const uint32_t mb_a   = sbase;                  // mbarrier (8B)
    const uint32_t shH_a  = sbase + SHH_OFF * 4;
    const uint32_t shR_a  = sbase + SHRED_OFF * 4;
    const uint32_t shW_a  = sbase + SHW_OFF * 4;
    float* shRed = sm + SHRED_OFF;

    // load this rank's 128x256 weights once (128 KB)
    {
        const float4* ws = (const float4*)(g_Wh2 + (size_t)jg * 32768);
        float4* wd = (float4*)(sm + SHW_OFF);
#pragma unroll
        for (int u = 0; u < 32; u++) wd[tid + u * 256] = ws[tid + u * 256];
    }
    if (tid == 0) {
        asm volatile("mbarrier.init.shared.b64 [%0], %1;" :: "r"(mb_a), "r"(GJ));
    }
    __syncthreads();
    asm volatile("barrier.cluster.arrive.aligned;" ::: "memory");
    asm volatile("barrier.cluster.wait.aligned;" ::: "memory");

    const int kh = tid >> 6;          // 0..3 (k chunk of 64)
    const int cpair = tid & 63;       // gate-col pair
    const int bl = tid & 3;           // finalize: batch-local
    const int jl = tid >> 2;          // finalize: unit-local (tid<128)
    float cell = 0.0f;

    for (int t = 0; t < Sn; t++) {
        // prefetch P[t] (contiguous 2KB per block) before the wait
        float p0, p1, p2, p3;
        if (tid < 128) {
            size_t base = ((((size_t)t * GB + ig) * GJ + jg) << 9) + jl * 4 + bl;
            p0 = g_P[base];
            p1 = g_P[base + 128];
            p2 = g_P[base + 256];
            p3 = g_P[base + 384];
        }
        if (t > 0) {
            // wait for h[t-1] from all 8 cluster ranks
            {
                uint32_t ph = (t - 1) & 1;
                asm volatile(
                    "{\n\t.reg .pred P;\n"
                    "WL_%=:\n\t"
                    "mbarrier.try_wait.parity.acquire.cluster.shared::cta.b64 P, [%0], %1, 0x989680;\n\t"
                    "@!P bra WL_%=;\n\t}"
                    :: "r"(mb_a), "r"(ph) : "memory");
            }
            // compute: thread (kh,cpair) -> 2 gate cols x 4 batches over 64 k
            uint32_t ha = shH_a + ((t - 1) & 1) * 4096 + kh * 1024; // k*16B
            uint32_t wa = shW_a + kh * 32768 + cpair * 8;           // k*512B
            unsigned long long a0b01 = 0, a0b23 = 0, a1b01 = 0, a1b23 = 0;
#pragma unroll 8
            for (int kk = 0; kk < 64; kk++) {
                unsigned long long h01, h23, w0d, w1d;
                uint32_t w0, w1;
                asm volatile("ld.shared.b64 %0, [%1];" : "=l"(h01) : "r"(ha));
                asm volatile("ld.shared.b64 %0, [%1];" : "=l"(h23) : "r"(ha + 8));
                asm volatile("ld.shared.v2.b32 {%0, %1}, [%2];" : "=r"(w0), "=r"(w1) : "r"(wa));
                asm("mov.b64 %0, {%1, %1};" : "=l"(w0d) : "r"(w0));
                asm("mov.b64 %0, {%1, %1};" : "=l"(w1d) : "r"(w1));
                asm("fma.rn.f32x2 %0, %1, %2, %0;" : "+l"(a0b01) : "l"(w0d), "l"(h01));
                asm("fma.rn.f32x2 %0, %1, %2, %0;" : "+l"(a0b23) : "l"(w0d), "l"(h23));
                asm("fma.rn.f32x2 %0, %1, %2, %0;" : "+l"(a1b01) : "l"(w1d), "l"(h01));
                asm("fma.rn.f32x2 %0, %1, %2, %0;" : "+l"(a1b23) : "l"(w1d), "l"(h23));
                ha += 16; wa += 512;
            }
            // partials -> shRed[kh][cpair][10]: {c0b01,c0b23,c1b01,c1b23}
            uint32_t ra = shR_a + kh * 2560 + cpair * 40;
            asm volatile("st.shared.b64 [%0], %1;"      :: "r"(ra),      "l"(a0b01));
            asm volatile("st.shared.b64 [%0], %1;"      :: "r"(ra + 8),  "l"(a0b23));
            asm volatile("st.shared.b64 [%0], %1;"      :: "r"(ra + 16), "l"(a1b01));
            asm volatile("st.shared.b64 [%0], %1;"      :: "r"(ra + 24), "l"(a1b23));
        }
        __syncthreads();
        // finalize: thread (bl, jl) owns unit j = jg*32+jl, batch b = ig*4+bl
        float hval = 0.0f;
        if (tid < 128) {
            float s0 = p0, s1 = p1, s2 = p2, s3 = p3;
            if (t > 0) {
#pragma unroll
                for (int g = 0; g < 4; g++) {
                    int off = (jl * 2 + (g >> 1)) * 10 + (g & 1) * 4 + bl;
                    float v = shRed[off] + shRed[640 + off]
                            + shRed[1280 + off] + shRed[1920 + off];
                    if (g == 0) s0 += v; else if (g == 1) s1 += v;
                    else if (g == 2) s2 += v; else s3 += v;
                }
            }
            float f  = 1.0f / (1.0f + __expf(-__cosf(s0)));
            float ii = 1.0f / (1.0f + __expf(-__cosf(s1)));
            float u  = tanhf(__cosf(s2));
            float o  = 1.0f / (1.0f + __expf(-__cosf(s3)));
            cell = f * cell + ii * u;
            hval = o * tanhf(cell);
            g_ysT[(size_t)t * BH + (size_t)(jg * 32 + jl) * 64 + ig * 4 + bl] = hval;
            if (t + 1 < Sn) {
                // publish h to all 8 cluster ranks' shH[t&1][j][bl]
                uint32_t la = shH_a + (t & 1) * 4096 + ((jg * 32 + jl) * 4 + bl) * 4;
#pragma unroll
                for (int r = 0; r < GJ; r++) {
                    uint32_t rm;
                    asm("mapa.shared::cluster.u32 %0, %1, %2;" : "=r"(rm) : "r"(la), "r"(r));
                    asm volatile("st.shared::cluster.f32 [%0], %1;" :: "r"(rm), "f"(hval));
                }
            }
        }
        __syncthreads();
        if (tid < GJ && t + 1 < Sn) {
            asm volatile("fence.acq_rel.cluster;" ::: "memory");
            uint32_t rb;
            asm("mapa.shared::cluster.u32 %0, %1, %2;" : "=r"(rb) : "r"(mb_a), "r"(tid));
            asm volatile("mbarrier.arrive.release.cluster.shared::cluster.b64 _, [%0];"
                         :: "r"(rb) : "memory");
        }
    }
    if (tid < 128) g_cT[(size_t)(jg * 32 + jl) * 64 + ig * 4 + bl] = cell;
}

// ---------------- phase 3a: qfeat = cos(ysT + phi), transpose to [B][S][H] ----------------
__global__ void __launch_bounds__(256) qfeat_kernel(const float* __restrict__ phi,
                                                    float* __restrict__ out) {
    __shared__ float smq[64 * 129];
    int s = blockIdx.x, half = blockIdx.y;
    int h0 = half * 128;
    int tid = threadIdx.x;
    const float* src = g_ysT + (size_t)s * BH + (size_t)h0 * 64;
#pragma unroll
    for (int r = 0; r < 32; r++) {
        int i = tid + r * 256;
        int h = i >> 6, b = i & 63;
        smq[b * 129 + h] = __cosf(src[i] + phi[h0 + h]);
    }
    __syncthreads();
#pragma unroll
    for (int r = 0; r < 32; r++) {
        int i = tid + r * 256;
        int b = i >> 7, h = i & 127;
        out[(size_t)b * (Sn * Hn) + (size_t)s * Hn + h0 + h] = smq[b * 129 + h];
    }
}

// ---------------- phase 3b: attention context + residual add ----------------
__global__ void attn_kernel(const float* __restrict__ tha, float* __restrict__ out) {
    int b = blockIdx.x, h = threadIdx.x;
    float th = tha[h];
    float se = 0.0f, sq = 0.0f;
    size_t base = (size_t)b * Sn * Hn + h;
#pragma unroll 4
    for (int s = 0; s < Sn; s++) {
        float q = out[base + (size_t)s * Hn];
        float e = __expf(tanhf(__cosf(q + th)));
        se += e; sq += e * q;
    }
    float ctx = sq / se;
#pragma unroll 4
    for (int s = 0; s < Sn; s++) {
        out[base + (size_t)s * Hn] += ctx;
    }
}

// ---------------- phase 3c: hx, cx tail ----------------
__global__ void tail_kernel(float* __restrict__ out) {
    int i = blockIdx.x * blockDim.x + threadIdx.x;
    if (i < BH) {
        int b = i >> 8, jx = i & 255;
        out[(size_t)Bn * Sn * Hn + i]      = g_ysT[(size_t)(Sn - 1) * BH + jx * 64 + b];
        out[(size_t)Bn * Sn * Hn + BH + i] = g_cT[jx * 64 + b];
    }
}

// ---------------- launch ----------------
extern "C" void kernel_launch(void* const* d_in, const int* in_sizes, int n_in,
                              void* d_out, int out_size) {
    const float* X   = (const float*)d_in[0];
    const float* Wf  = (const float*)d_in[1];
    const float* bf  = (const float*)d_in[2];
    const float* Wi  = (const float*)d_in[3];
    const float* bi  = (const float*)d_in[4];
    const float* Wu  = (const float*)d_in[5];
    const float* bu  = (const float*)d_in[6];
    const float* Wo  = (const float*)d_in[7];
    const float* bo  = (const float*)d_in[8];
    const float* thf = (const float*)d_in[9];
    const float* thi = (const float*)d_in[10];
    const float* thu = (const float*)d_in[11];
    const float* tho = (const float*)d_in[12];
    const float* phi = (const float*)d_in[13];
    const float* tha = (const float*)d_in[14];
    float* out = (float*)d_out;

    cudaFuncSetAttribute(lstm_main_kernel,
                         cudaFuncAttributeMaxDynamicSharedMemorySize, SMEM_MAIN_BYTES);

    prep_kernel<<<1024, 256>>>(Wf, bf, Wi, bi, Wu, bu, Wo, bo, thf, thi, thu, tho);
    xproj_kernel<<<dim3(8, 512), 256>>>(X);
    lstm_main_kernel<<<NBLK, 256, SMEM_MAIN_BYTES>>>();
    qfeat_kernel<<<dim3(Sn, 2), 256>>>(phi, out);
    attn_kernel<<<Bn, 256>>>(tha, out);
    if (out_size >= Bn * Sn * Hn + 2 * BH) {
        tail_kernel<<<64, 256>>>(out);
    }
}

// round 4
// speedup vs baseline: 1.4142x; 1.2779x over previous
#include <cuda_runtime.h>
#include <cstdint>

// Problem dims
#define Sn 1024
#define Bn 64
#define Dn 256
#define Hn 256
#define G4 1024               // 4*H gate columns
#define BH (Bn*Hn)            // 16384
#define GB 16                 // batch groups (4 batches each)
#define GJ 8                  // j groups (32 hidden units each) == cluster size
#define NBLK (GB*GJ)          // 128 blocks

// ---------------- scratch (static device allocations only) ----------------
__device__ float g_P[(size_t)Sn * G4 * Bn];     // [t][ig][jg][g][jl][bl] (256 MB)
__device__ float g_ysT[(size_t)Sn * Hn * Bn];   // h history [t][j][b] (64 MB)
__device__ float g_Wxr[G4 * Dn];                // [c][k] x-part weights (c=g*256+j)
__device__ float g_Wh2[GJ * Hn * 128];          // [jg][kc][kl][cg][cp][e] reg-GEMM layout
__device__ float g_thb[G4];                     // b + theta folded
__device__ float g_cT[Hn * Bn];                 // final cell state [j][b]

// ---------------- prep ----------------
__global__ void prep_kernel(const float* Wf, const float* bf,
                            const float* Wi, const float* bi,
                            const float* Wu, const float* bu,
                            const float* Wo, const float* bo,
                            const float* thf, const float* thi,
                            const float* thu, const float* tho) {
    int idx = blockIdx.x * blockDim.x + threadIdx.x;
    const float* W[4]  = {Wf, Wi, Wu, Wo};
    const float* bb[4] = {bf, bi, bu, bo};
    const float* th[4] = {thf, thi, thu, tho};
    if (idx < G4 * Dn) {                        // Wxr[c][k] = W_g[j][k], c=g*256+j
        int c = idx >> 8, k = idx & 255;
        int g = c >> 8, j = c & 255;
        g_Wxr[idx] = W[g][j * 512 + k];
    }
    if (idx < GJ * Hn * 128) {
        // f = (((jg*8+kc)*32+kl)*32+cg)*4 + cp*2 + e
        int e  = idx & 1;
        int cp = (idx >> 1) & 1;
        int cg = (idx >> 2) & 31;
        int kl = (idx >> 7) & 31;
        int kc = (idx >> 12) & 7;
        int jg = idx >> 15;
        int j = jg * 32 + cg;
        int k = kc * 32 + kl;
        int g = cp * 2 + e;
        g_Wh2[idx] = W[g][j * 512 + 256 + k];
    }
    if (idx < G4) {
        int g = idx >> 8, j = idx & 255;
        g_thb[idx] = bb[g][j] + th[g][j];
    }
}

// ---------------- phase 1: X projection SGEMM (65536 x 1024 x 256) ----------------
__global__ void __launch_bounds__(256) xproj_kernel(const float* __restrict__ X) {
    __shared__ float As[16][128];
    __shared__ float Bs[16][128];
    int tid = threadIdx.x;
    int n0 = blockIdx.x * 128;
    int m0 = blockIdx.y * 128;
    int tx = tid & 15, ty = tid >> 4;
    float acc[8][8];
#pragma unroll
    for (int i = 0; i < 8; i++)
#pragma unroll
        for (int j = 0; j < 8; j++) acc[i][j] = 0.0f;

    for (int k0 = 0; k0 < 256; k0 += 16) {
#pragma unroll
        for (int i = 0; i < 2; i++) {
            int fidx = tid + i * 256;
            int r = fidx >> 2, kq = (fidx & 3) * 4;
            float4 va = *(const float4*)&X[(size_t)(m0 + r) * 256 + k0 + kq];
            As[kq + 0][r] = va.x; As[kq + 1][r] = va.y;
            As[kq + 2][r] = va.z; As[kq + 3][r] = va.w;
            float4 vb = *(const float4*)&g_Wxr[(size_t)(n0 + r) * 256 + k0 + kq];
            Bs[kq + 0][r] = vb.x; Bs[kq + 1][r] = vb.y;
            Bs[kq + 2][r] = vb.z; Bs[kq + 3][r] = vb.w;
        }
        __syncthreads();
#pragma unroll
        for (int kk = 0; kk < 16; kk++) {
            float a[8], b[8];
#pragma unroll
            for (int i = 0; i < 8; i++) a[i] = As[kk][ty * 8 + i];
#pragma unroll
            for (int j = 0; j < 8; j++) b[j] = Bs[kk][tx * 8 + j];
#pragma unroll
            for (int i = 0; i < 8; i++)
#pragma unroll
                for (int j = 0; j < 8; j++) acc[i][j] += a[i] * b[j];
        }
        __syncthreads();
    }
#pragma unroll
    for (int i = 0; i < 8; i++) {
        int m = m0 + ty * 8 + i;
        int t = m >> 6, b = m & 63;
        int ig = b >> 2, bl = b & 3;
#pragma unroll
        for (int j = 0; j < 8; j++) {
            int c = n0 + tx * 8 + j;
            int g = c >> 8, jj = c & 255;
            int jg = jj >> 5, jl = jj & 31;
            size_t idx = ((((size_t)t * GB + ig) * GJ + jg) << 9) + g * 128 + jl * 4 + bl;
            g_P[idx] = acc[i][j] + g_thb[c];
        }
    }
}

// ---------------- phase 2: clustered persistent LSTM recurrence ----------------
// 128 blocks = 16 clusters of 8. Cluster = batch group (4 batches).
// Rank jg owns 32 hidden units (128 gate cols). Weights live in REGISTERS
// (64 u64 packed gate-col pairs per thread). h exchange via DSMEM +
// cluster mbarrier (double-buffered shH, parity barrier). No cluster fence.
// smem float layout: [0..3] mbar/pad | shH[2][256][4] | shRed (u64[8][324])
#define SHH_OFF   4
#define SHRED_OFF (SHH_OFF + 2048)
#define SMEM_MAIN_FLOATS (SHRED_OFF + 8 * 324 * 2)
#define SMEM_MAIN_BYTES  (SMEM_MAIN_FLOATS * 4)

__device__ __forceinline__ float fast_sig_cos(float x) {
    float c = __cosf(x);
    return __fdividef(1.0f, 1.0f + __expf(-c));
}
__device__ __forceinline__ float fast_tanh(float x) {
    return 1.0f - __fdividef(2.0f, __expf(2.0f * x) + 1.0f);
}

__global__ void __launch_bounds__(256, 1) __cluster_dims__(GJ, 1, 1)
lstm_main_kernel() {
    extern __shared__ float sm[];
    int tid = threadIdx.x;
    uint32_t jg;
    asm("mov.u32 %0, %%cluster_ctarank;" : "=r"(jg));
    int ig = blockIdx.x >> 3;

    uint32_t sbase;
    asm("{ .reg .u64 t0; cvta.to.shared.u64 t0, %1; cvt.u32.u64 %0, t0; }"
        : "=r"(sbase) : "l"(sm));
    const uint32_t mb_a  = sbase;                  // mbarrier (8B)
    const uint32_t shH_a = sbase + SHH_OFF * 4;
    const uint32_t shR_a = sbase + SHRED_OFF * 4;

    const int kc = tid >> 5;          // k chunk (0..7, 32 k each)
    const int cg = tid & 31;          // unit-local jl this thread computes
    const int bl = tid & 3;           // finalize: batch-local
    const int jl = tid >> 2;          // finalize: unit-local (tid<128)

    // preload weights into registers: 64 u64 = 128 floats
    unsigned long long w0[32], w1[32];
    {
        const ulonglong2* ws = (const ulonglong2*)(g_Wh2 + (((size_t)jg * 8 + kc) << 12));
#pragma unroll
        for (int kl = 0; kl < 32; kl++) {
            ulonglong2 v = ws[kl * 32 + cg];
            w0[kl] = v.x; w1[kl] = v.y;
        }
    }
    if (tid == 0) {
        asm volatile("mbarrier.init.shared.b64 [%0], %1;" :: "r"(mb_a), "r"(GJ));
    }
    __syncthreads();
    asm volatile("barrier.cluster.arrive.aligned;" ::: "memory");
    asm volatile("barrier.cluster.wait.aligned;" ::: "memory");

    float cell = 0.0f;

    for (int t = 0; t < Sn; t++) {
        // prefetch P[t] (contiguous 2KB per block) before the wait
        float p0, p1, p2, p3;
        if (tid < 128) {
            size_t base = ((((size_t)t * GB + ig) * GJ + jg) << 9) + jl * 4 + bl;
            p0 = g_P[base];
            p1 = g_P[base + 128];
            p2 = g_P[base + 256];
            p3 = g_P[base + 384];
        }
        if (t > 0) {
            // wait for h[t-1] from all 8 cluster ranks
            {
                uint32_t ph = (t - 1) & 1;
                asm volatile(
                    "{\n\t.reg .pred P;\n"
                    "WL_%=:\n\t"
                    "mbarrier.try_wait.parity.acquire.cluster.shared::cta.b64 P, [%0], %1, 0x989680;\n\t"
                    "@!P bra WL_%=;\n\t}"
                    :: "r"(mb_a), "r"(ph) : "memory");
            }
            // compute: thread (kc,cg) -> 4 gate cols (unit cg) x 4 batches over 32 k
            uint32_t ha = shH_a + ((t - 1) & 1) * 4096 + kc * 512;
            unsigned long long a00 = 0, a01 = 0, a02 = 0, a03 = 0;  // cp0 (f,i) x b
            unsigned long long a10 = 0, a11 = 0, a12 = 0, a13 = 0;  // cp1 (u,o) x b
#pragma unroll
            for (int kl = 0; kl < 32; kl++) {
                float hx, hy, hz, hw;
                asm volatile("ld.shared.v4.f32 {%0,%1,%2,%3}, [%4];"
                             : "=f"(hx), "=f"(hy), "=f"(hz), "=f"(hw) : "r"(ha));
                unsigned long long h0, h1, h2, h3;
                asm("mov.b64 %0, {%1, %1};" : "=l"(h0) : "f"(hx));
                asm("mov.b64 %0, {%1, %1};" : "=l"(h1) : "f"(hy));
                asm("mov.b64 %0, {%1, %1};" : "=l"(h2) : "f"(hz));
                asm("mov.b64 %0, {%1, %1};" : "=l"(h3) : "f"(hw));
                asm("fma.rn.f32x2 %0, %1, %2, %0;" : "+l"(a00) : "l"(w0[kl]), "l"(h0));
                asm("fma.rn.f32x2 %0, %1, %2, %0;" : "+l"(a01) : "l"(w0[kl]), "l"(h1));
                asm("fma.rn.f32x2 %0, %1, %2, %0;" : "+l"(a02) : "l"(w0[kl]), "l"(h2));
                asm("fma.rn.f32x2 %0, %1, %2, %0;" : "+l"(a03) : "l"(w0[kl]), "l"(h3));
                asm("fma.rn.f32x2 %0, %1, %2, %0;" : "+l"(a10) : "l"(w1[kl]), "l"(h0));
                asm("fma.rn.f32x2 %0, %1, %2, %0;" : "+l"(a11) : "l"(w1[kl]), "l"(h1));
                asm("fma.rn.f32x2 %0, %1, %2, %0;" : "+l"(a12) : "l"(w1[kl]), "l"(h2));
                asm("fma.rn.f32x2 %0, %1, %2, %0;" : "+l"(a13) : "l"(w1[kl]), "l"(h3));
                ha += 16;
            }
            // partials -> shRed u64[kc*324 + cp*5 + b], cp = cg*2 + cpl
            {
                uint32_t r0 = shR_a + (kc * 324 + (cg * 2) * 5) * 8;
                asm volatile("st.shared.b64 [%0], %1;" :: "r"(r0),      "l"(a00));
                asm volatile("st.shared.b64 [%0], %1;" :: "r"(r0 + 8),  "l"(a01));
                asm volatile("st.shared.b64 [%0], %1;" :: "r"(r0 + 16), "l"(a02));
                asm volatile("st.shared.b64 [%0], %1;" :: "r"(r0 + 24), "l"(a03));
                uint32_t r1 = r0 + 40;
                asm volatile("st.shared.b64 [%0], %1;" :: "r"(r1),      "l"(a10));
                asm volatile("st.shared.b64 [%0], %1;" :: "r"(r1 + 8),  "l"(a11));
                asm volatile("st.shared.b64 [%0], %1;" :: "r"(r1 + 16), "l"(a12));
                asm volatile("st.shared.b64 [%0], %1;" :: "r"(r1 + 24), "l"(a13));
            }
        }
        __syncthreads();
        // finalize: thread (jl, bl) owns unit j = jg*32+jl, batch b = ig*4+bl
        float hval = 0.0f;
        if (tid < 128) {
            float s0 = p0, s1 = p1, s2 = p2, s3 = p3;
            if (t > 0) {
                unsigned long long sfi = 0, suo = 0;
                uint32_t rfi = shR_a + ((jl * 2) * 5 + bl) * 8;
                uint32_t ruo = rfi + 40;
#pragma unroll
                for (int k2 = 0; k2 < 8; k2++) {
                    unsigned long long vfi, vuo;
                    asm volatile("ld.shared.b64 %0, [%1];" : "=l"(vfi) : "r"(rfi));
                    asm volatile("ld.shared.b64 %0, [%1];" : "=l"(vuo) : "r"(ruo));
                    asm("add.rn.f32x2 %0, %0, %1;" : "+l"(sfi) : "l"(vfi));
                    asm("add.rn.f32x2 %0, %0, %1;" : "+l"(suo) : "l"(vuo));
                    rfi += 324 * 8; ruo += 324 * 8;
                }
                float vf, vi, vu, vo;
                asm("mov.b64 {%0, %1}, %2;" : "=f"(vf), "=f"(vi) : "l"(sfi));
                asm("mov.b64 {%0, %1}, %2;" : "=f"(vu), "=f"(vo) : "l"(suo));
                s0 += vf; s1 += vi; s2 += vu; s3 += vo;
            }
            float f  = fast_sig_cos(s0);
            float ii = fast_sig_cos(s1);
            float u  = fast_tanh(__cosf(s2));
            float o  = fast_sig_cos(s3);
            cell = f * cell + ii * u;
            hval = o * fast_tanh(cell);
            g_ysT[(size_t)t * BH + (size_t)(jg * 32 + jl) * 64 + ig * 4 + bl] = hval;
        }
        if (tid < 128 && t + 1 < Sn) {
            // pack batch pairs and publish to all 8 ranks' shH[t&1]
            float partner = __shfl_down_sync(0xffffffffu, hval, 1);
            if ((bl & 1) == 0) {
                unsigned long long pair;
                asm("mov.b64 %0, {%1, %2};" : "=l"(pair) : "f"(hval), "f"(partner));
                uint32_t la = shH_a + (t & 1) * 4096 + ((jg * 32 + jl) * 4 + bl) * 4;
#pragma unroll
                for (int r = 0; r < GJ; r++) {
                    uint32_t rm;
                    asm("mapa.shared::cluster.u32 %0, %1, %2;" : "=r"(rm) : "r"(la), "r"(r));
                    asm volatile("st.shared::cluster.b64 [%0], %1;" :: "r"(rm), "l"(pair));
                }
            }
        }
        __syncthreads();
        if (tid < GJ && t + 1 < Sn) {
            uint32_t rb;
            asm("mapa.shared::cluster.u32 %0, %1, %2;" : "=r"(rb) : "r"(mb_a), "r"(tid));
            asm volatile("mbarrier.arrive.release.cluster.shared::cluster.b64 _, [%0];"
                         :: "r"(rb) : "memory");
        }
    }
    if (tid < 128) g_cT[(size_t)(jg * 32 + jl) * 64 + ig * 4 + bl] = cell;
}

// ---------------- phase 3a: qfeat = cos(ysT + phi), transpose to [B][S][H] ----------------
__global__ void __launch_bounds__(256) qfeat_kernel(const float* __restrict__ phi,
                                                    float* __restrict__ out) {
    __shared__ float smq[64 * 129];
    int s = blockIdx.x, half = blockIdx.y;
    int h0 = half * 128;
    int tid = threadIdx.x;
    const float* src = g_ysT + (size_t)s * BH + (size_t)h0 * 64;
#pragma unroll
    for (int r = 0; r < 32; r++) {
        int i = tid + r * 256;
        int h = i >> 6, b = i & 63;
        smq[b * 129 + h] = __cosf(src[i] + phi[h0 + h]);
    }
    __syncthreads();
#pragma unroll
    for (int r = 0; r < 32; r++) {
        int i = tid + r * 256;
        int b = i >> 7, h = i & 127;
        out[(size_t)b * (Sn * Hn) + (size_t)s * Hn + h0 + h] = smq[b * 129 + h];
    }
}

// ---------------- phase 3b: attention context + residual add ----------------
__global__ void __launch_bounds__(128) attn_kernel(const float* __restrict__ tha,
                                                   float* __restrict__ out) {
    int b = blockIdx.x;
    int h = blockIdx.y * 128 + threadIdx.x;
    float th = tha[h];
    float se = 0.0f, sq = 0.0f;
    size_t base = (size_t)b * Sn * Hn + h;
#pragma unroll 4
    for (int s = 0; s < Sn; s++) {
        float q = out[base + (size_t)s * Hn];
        float e = __expf(fast_tanh(__cosf(q + th)));
        se += e; sq += e * q;
    }
    float ctx = sq / se;
#pragma unroll 4
    for (int s = 0; s < Sn; s++) {
        out[base + (size_t)s * Hn] += ctx;
    }
}

// ---------------- phase 3c: hx, cx tail ----------------
__global__ void tail_kernel(float* __restrict__ out) {
    int i = blockIdx.x * blockDim.x + threadIdx.x;
    if (i < BH) {
        int b = i >> 8, jx = i & 255;
        out[(size_t)Bn * Sn * Hn + i]      = g_ysT[(size_t)(Sn - 1) * BH + jx * 64 + b];
        out[(size_t)Bn * Sn * Hn + BH + i] = g_cT[jx * 64 + b];
    }
}

// ---------------- launch ----------------
extern "C" void kernel_launch(void* const* d_in, const int* in_sizes, int n_in,
                              void* d_out, int out_size) {
    const float* X   = (const float*)d_in[0];
    const float* Wf  = (const float*)d_in[1];
    const float* bf  = (const float*)d_in[2];
    const float* Wi  = (const float*)d_in[3];
    const float* bi  = (const float*)d_in[4];
    const float* Wu  = (const float*)d_in[5];
    const float* bu  = (const float*)d_in[6];
    const float* Wo  = (const float*)d_in[7];
    const float* bo  = (const float*)d_in[8];
    const float* thf = (const float*)d_in[9];
    const float* thi = (const float*)d_in[10];
    const float* thu = (const float*)d_in[11];
    const float* tho = (const float*)d_in[12];
    const float* phi = (const float*)d_in[13];
    const float* tha = (const float*)d_in[14];
    float* out = (float*)d_out;

    cudaFuncSetAttribute(lstm_main_kernel,
                         cudaFuncAttributeMaxDynamicSharedMemorySize, SMEM_MAIN_BYTES);

    prep_kernel<<<1024, 256>>>(Wf, bf, Wi, bi, Wu, bu, Wo, bo, thf, thi, thu, tho);
    xproj_kernel<<<dim3(8, 512), 256>>>(X);
    lstm_main_kernel<<<NBLK, 256, SMEM_MAIN_BYTES>>>();
    qfeat_kernel<<<dim3(Sn, 2), 256>>>(phi, out);
    attn_kernel<<<dim3(Bn, 2), 128>>>(tha, out);
    if (out_size >= Bn * Sn * Hn + 2 * BH) {
        tail_kernel<<<64, 256>>>(out);
    }
}